// round 8
// baseline (speedup 1.0000x reference)
#include <cuda_runtime.h>
#include <math.h>
#include <stdint.h>

#define D_MODEL     256
#define EXPERT_DIM  512
#define NUM_EXPERTS 8
#define T_TOKENS    4096
#define TILE_T      64
#define EGRID       148
#define ETHREADS    512

#define XS_STRIDE   260
#define HS_STRIDE   68
#define W1S_STRIDE  72
#define W2S_STRIDE  264
#define STAGE_FLOATS 4224            // max(32*72, 16*264)
#define NSLOT        3
#define NSTAGE       96              // 8 chunks * (8 W1 + 4 W2)
#define SMEM_FLOATS  (TILE_T*XS_STRIDE + TILE_T*HS_STRIDE + NSLOT*STAGE_FLOATS + 224)
#define SMEM_BYTES   (SMEM_FLOATS * 4)

// ---- device scratch ----
__device__ int   g_cnt[NUM_EXPERTS];
__device__ int   g_tok [NUM_EXPERTS][T_TOKENS];
__device__ float g_wt  [NUM_EXPERTS][T_TOKENS];
__device__ int   g_slot[NUM_EXPERTS][T_TOKENS];
__device__ float g_scratch[2][T_TOKENS][D_MODEL];
__device__ float g_W1c[NUM_EXPERTS * D_MODEL * EXPERT_DIM];   // tf32-rounded
__device__ float g_W2c[NUM_EXPERTS * EXPERT_DIM * D_MODEL];   // tf32-rounded
__device__ int   g_done;
__device__ int   g_done2;

// ---------------------------------------------------------------------------
__device__ __forceinline__ float tf32r(float x) {
    uint32_t u;
    asm("cvt.rna.tf32.f32 %0, %1;" : "=r"(u) : "f"(x));
    return __uint_as_float(u);
}

__device__ __forceinline__ void mma_tf32(float c[4], const float a[4],
                                         float b0, float b1) {
    const uint32_t* A = reinterpret_cast<const uint32_t*>(a);
    uint32_t B0 = __float_as_uint(b0), B1 = __float_as_uint(b1);
    asm volatile(
        "mma.sync.aligned.m16n8k8.row.col.f32.tf32.tf32.f32 "
        "{%0,%1,%2,%3}, {%4,%5,%6,%7}, {%8,%9}, {%0,%1,%2,%3};\n"
        : "+f"(c[0]), "+f"(c[1]), "+f"(c[2]), "+f"(c[3])
        : "r"(A[0]), "r"(A[1]), "r"(A[2]), "r"(A[3]), "r"(B0), "r"(B1));
}

__device__ __forceinline__ void cp16(uint32_t dst, const float* src) {
    asm volatile("cp.async.ca.shared.global [%0], [%1], 16;" :: "r"(dst), "l"(src));
}
__device__ __forceinline__ void cp_commit() { asm volatile("cp.async.commit_group;"); }
__device__ __forceinline__ void cp_wait1()  { asm volatile("cp.async.wait_group 1;"); }
__device__ __forceinline__ void cp_wait0()  { asm volatile("cp.async.wait_group 0;"); }

// ---------------------------------------------------------------------------
// Fused init: blocks [0,512) route; blocks [512,2560) tf32-convert W1/W2.
__global__ void init_kernel(const float* __restrict__ x,
                            const float* __restrict__ Wg,
                            const float* __restrict__ bg,
                            const float* __restrict__ bias,
                            const float* __restrict__ W1,
                            const float* __restrict__ W2) {
    int bid = blockIdx.x, tid = threadIdx.x;

    if (bid < 512) {
        // ---------------- routing: one warp per token ----------------
        int warp = (bid * 256 + tid) >> 5;
        int lane = tid & 31;
        int t = warp;
        const float* xr = x + (size_t)t * D_MODEL;
        float acc[NUM_EXPERTS];
#pragma unroll
        for (int e = 0; e < NUM_EXPERTS; e++) acc[e] = 0.f;
#pragma unroll
        for (int j = 0; j < D_MODEL / 32; j++) {
            int k = lane + j * 32;
            float xv = xr[k];
            const float4* wrow = (const float4*)(Wg + (size_t)k * NUM_EXPERTS);
            float4 w0 = wrow[0], w1 = wrow[1];
            acc[0] += xv * w0.x; acc[1] += xv * w0.y;
            acc[2] += xv * w0.z; acc[3] += xv * w0.w;
            acc[4] += xv * w1.x; acc[5] += xv * w1.y;
            acc[6] += xv * w1.z; acc[7] += xv * w1.w;
        }
#pragma unroll
        for (int e = 0; e < NUM_EXPERTS; e++)
#pragma unroll
            for (int off = 16; off > 0; off >>= 1)
                acc[e] += __shfl_xor_sync(0xffffffffu, acc[e], off);
        if (lane == 0) {
            float best = -INFINITY, second = -INFINITY;
            int b0 = 0, b1 = 0;
#pragma unroll
            for (int e = 0; e < NUM_EXPERTS; e++) {
                float v = acc[e] + bg[e] + bias[e];
                if (v > best)        { second = best; b1 = b0; best = v; b0 = e; }
                else if (v > second) { second = v; b1 = e; }
            }
            float e1  = expf(second - best);
            float inv = 1.f / (1.f + e1);
            int p0 = atomicAdd(&g_cnt[b0], 1);
            g_tok[b0][p0] = t; g_wt[b0][p0] = inv;      g_slot[b0][p0] = 0;
            int p1 = atomicAdd(&g_cnt[b1], 1);
            g_tok[b1][p1] = t; g_wt[b1][p1] = e1 * inv; g_slot[b1][p1] = 1;
        }
    } else {
        // ---------------- tf32 weight convert (straight layout) --------
        int j = (bid - 512) * 256 + tid;        // 0 .. 524287 float4s
        const int N4 = NUM_EXPERTS * D_MODEL * EXPERT_DIM / 4;
        float4 v; float4* dst;
        if (j < N4) { v = ((const float4*)W1)[j]; dst = (float4*)g_W1c + j; }
        else        { v = ((const float4*)W2)[j - N4]; dst = (float4*)g_W2c + (j - N4); }
        v.x = tf32r(v.x); v.y = tf32r(v.y); v.z = tf32r(v.z); v.w = tf32r(v.w);
        *dst = v;
    }
}

// ---------------------------------------------------------------------------
// 148 blocks x 512 threads (16 warps = 4m x 4n). <=136 items of 64 tokens.
// 96-stage cp.async ring (3 slots), one barrier per stage, fused combine.
__global__ void __launch_bounds__(ETHREADS, 1)
expert_kernel(const float* __restrict__ x,
              const float* __restrict__ b1,
              const float* __restrict__ b2,
              float* __restrict__ out) {
    extern __shared__ float sm[];
    float* Xs  = sm;                                  // [64][260]
    float* Hs  = sm + TILE_T * XS_STRIDE;             // [64][68]
    float* Wst = Hs + TILE_T * HS_STRIDE;             // [3][4224]
    int*   s_tok  = (int*)(Wst + NSLOT * STAGE_FLOATS);
    float* s_wt   = (float*)(s_tok + TILE_T);
    int*   s_slot = (int*)(s_wt + TILE_T);

    int tid  = threadIdx.x;
    int wid  = tid >> 5;
    int wm   = wid >> 2;        // 0..3 -> m-tile rows 16*wm..+16
    int wn   = wid & 3;         // 0..3
    int lane = tid & 31;
    int g = lane >> 2, t = lane & 3;
    int rA = 16 * wm + g;

    // inline scheduler
    int cnt[NUM_EXPERTS], off[NUM_EXPERTS + 1];
    off[0] = 0;
#pragma unroll
    for (int e = 0; e < NUM_EXPERTS; e++) {
        cnt[e] = g_cnt[e];
        off[e + 1] = off[e] + (cnt[e] + TILE_T - 1) / TILE_T;
    }
    int total = off[NUM_EXPERTS];

    uint32_t wst_sa = (uint32_t)__cvta_generic_to_shared(Wst);

    for (int it = blockIdx.x; it < total; it += EGRID) {
        int e = 0;
#pragma unroll
        for (int k = 1; k < NUM_EXPERTS; k++)
            if (it >= off[k]) e = k;
        int start = (it - off[e]) * TILE_T;
        int m = min(TILE_T, cnt[e] - start);

        const float* W1p = g_W1c + (size_t)e * D_MODEL * EXPERT_DIM;
        const float* W2p = g_W2c + (size_t)e * EXPERT_DIM * D_MODEL;
        const float* b1e = b1 + e * EXPERT_DIM;
        const float* b2e = b2 + e * D_MODEL;

        // stage s: c = s/12, j = s%12.
        //  j<8 : W1 K-rows 32j..+32, cols c*64..+64 -> [32][72]
        //  j>=8: W2 K-rows c*64+16(j-8)..+16, all 256 cols -> [16][264]
        auto issue_stage = [&](int s) {
            int slot = s % NSLOT;
            int c = s / 12, j = s % 12;
            uint32_t base = wst_sa + (uint32_t)(slot * STAGE_FLOATS) * 4u;
            if (j < 8) {
                int o = tid;                        // 512 cp16, one each
                int row = o >> 4, q = o & 15;
                cp16(base + (uint32_t)(row * W1S_STRIDE + q * 4) * 4u,
                     W1p + (size_t)(j * 32 + row) * EXPERT_DIM + c * 64 + q * 4);
            } else {
#pragma unroll
                for (int i = 0; i < 2; i++) {       // 1024 cp16
                    int o = tid + 512 * i;
                    int row = o >> 6, q = o & 63;
                    cp16(base + (uint32_t)(row * W2S_STRIDE + q * 4) * 4u,
                         W2p + (size_t)(c * 64 + (j - 8) * 16 + row) * D_MODEL + q * 4);
                }
            }
        };

        __syncthreads();
        if (tid < TILE_T) {
            if (tid < m) {
                s_tok[tid]  = g_tok [e][start + tid];
                s_wt[tid]   = g_wt  [e][start + tid];
                s_slot[tid] = g_slot[e][start + tid];
            } else {
                s_tok[tid] = 0; s_wt[tid] = 0.f; s_slot[tid] = 0;
            }
        }
        issue_stage(0); cp_commit();
        issue_stage(1); cp_commit();
        __syncthreads();

        // gather X tile (tf32-rounded): 64 rows x 64 float4 = 4096
#pragma unroll
        for (int i = 0; i < 8; i++) {
            int idx = tid + i * ETHREADS;
            int row = idx >> 6, q = idx & 63;
            float4 v = make_float4(0.f, 0.f, 0.f, 0.f);
            if (row < m)
                v = ((const float4*)(x + (size_t)s_tok[row] * D_MODEL))[q];
            v.x = tf32r(v.x); v.y = tf32r(v.y); v.z = tf32r(v.z); v.w = tf32r(v.w);
            *((float4*)&Xs[row * XS_STRIDE + q * 4]) = v;
        }

        float acc2[8][4];
#pragma unroll
        for (int f = 0; f < 8; f++)
#pragma unroll
            for (int r = 0; r < 4; r++) acc2[f][r] = 0.f;
        float c1[2][4];

        for (int s = 0; s < NSTAGE; s++) {
            if (s >= NSTAGE - 2) cp_wait0(); else cp_wait1();
            __syncthreads();
            if (s + 2 < NSTAGE) { issue_stage(s + 2); cp_commit(); }

            int c = s / 12, j = s % 12;
            const float* Ws = Wst + (s % NSLOT) * STAGE_FLOATS;

            if (j < 8) {
                if (j == 0) {
#pragma unroll
                    for (int f = 0; f < 2; f++)
#pragma unroll
                        for (int r = 0; r < 4; r++) c1[f][r] = 0.f;
                }
#pragma unroll
                for (int ks = 0; ks < 4; ks++) {
                    int k0 = j * 32 + ks * 8 + t;
                    float a[4];
                    a[0] = Xs[rA * XS_STRIDE + k0];
                    a[1] = Xs[(rA + 8) * XS_STRIDE + k0];
                    a[2] = Xs[rA * XS_STRIDE + k0 + 4];
                    a[3] = Xs[(rA + 8) * XS_STRIDE + k0 + 4];
#pragma unroll
                    for (int f = 0; f < 2; f++) {
                        int col = 16 * wn + 8 * f + g;
                        float b0 = Ws[(ks * 8 + t) * W1S_STRIDE + col];
                        float bv = Ws[(ks * 8 + t + 4) * W1S_STRIDE + col];
                        mma_tf32(c1[f], a, b0, bv);
                    }
                }
                if (j == 7) {
                    // bias + relu + tf32 round -> Hs (read after next sync)
#pragma unroll
                    for (int f = 0; f < 2; f++) {
                        int col = 16 * wn + 8 * f + 2 * t;
                        float bv0 = b1e[c * 64 + col];
                        float bv1 = b1e[c * 64 + col + 1];
                        float2 lo, hi;
                        lo.x = tf32r(fmaxf(c1[f][0] + bv0, 0.f));
                        lo.y = tf32r(fmaxf(c1[f][1] + bv1, 0.f));
                        hi.x = tf32r(fmaxf(c1[f][2] + bv0, 0.f));
                        hi.y = tf32r(fmaxf(c1[f][3] + bv1, 0.f));
                        *((float2*)&Hs[rA * HS_STRIDE + col])       = lo;
                        *((float2*)&Hs[(rA + 8) * HS_STRIDE + col]) = hi;
                    }
                }
            } else {
#pragma unroll
                for (int ks = 0; ks < 2; ks++) {
                    int kc = (j - 8) * 16 + ks * 8 + t;
                    float a[4];
                    a[0] = Hs[rA * HS_STRIDE + kc];
                    a[1] = Hs[(rA + 8) * HS_STRIDE + kc];
                    a[2] = Hs[rA * HS_STRIDE + kc + 4];
                    a[3] = Hs[(rA + 8) * HS_STRIDE + kc + 4];
#pragma unroll
                    for (int f = 0; f < 8; f++) {
                        int col = 64 * wn + 8 * f + g;
                        float b0 = Ws[(ks * 8 + t) * W2S_STRIDE + col];
                        float bv = Ws[(ks * 8 + t + 4) * W2S_STRIDE + col];
                        mma_tf32(acc2[f], a, b0, bv);
                    }
                }
            }
        }

        // ---- epilogue: scratch[slot][tok][col] = w * (acc + b2) ----
#pragma unroll
        for (int hrow = 0; hrow < 2; hrow++) {
            int r = rA + 8 * hrow;
            if (r < m) {
                float wgt = s_wt[r];
                float* op = &g_scratch[s_slot[r]][s_tok[r]][0];
#pragma unroll
                for (int f = 0; f < 8; f++) {
                    int col = 64 * wn + 8 * f + 2 * t;
                    float2 o;
                    o.x = wgt * (acc2[f][2 * hrow + 0] + b2e[col]);
                    o.y = wgt * (acc2[f][2 * hrow + 1] + b2e[col + 1]);
                    *((float2*)(op + col)) = o;
                }
            }
        }
    }

    // ================= spin barrier + fused combine =================
    __threadfence();
    __syncthreads();
    if (tid == 0) {
        atomicAdd(&g_done, 1);
        while (*((volatile int*)&g_done) < EGRID) { }
    }
    __syncthreads();
    __threadfence();

    const float4* s0 = (const float4*)g_scratch[0];
    const float4* s1 = (const float4*)g_scratch[1];
    float4* o4 = (float4*)out;
    const int N4 = T_TOKENS * D_MODEL / 4;
    for (int i = blockIdx.x * ETHREADS + tid; i < N4; i += EGRID * ETHREADS) {
        float4 a = s0[i], b = s1[i];
        float4 o;
        o.x = a.x + b.x; o.y = a.y + b.y; o.z = a.z + b.z; o.w = a.w + b.w;
        o4[i] = o;
    }

    // ---- last block resets counters for the next graph replay ----
    __threadfence();
    __syncthreads();
    if (tid == 0) {
        int v = atomicAdd(&g_done2, 1);
        if (v == EGRID - 1) {
            g_done = 0; g_done2 = 0;
#pragma unroll
            for (int e = 0; e < NUM_EXPERTS; e++) g_cnt[e] = 0;
        }
    }
}

// ---------------------------------------------------------------------------
extern "C" void kernel_launch(void* const* d_in, const int* in_sizes, int n_in,
                              void* d_out, int out_size) {
    const float* x    = (const float*)d_in[0];
    const float* Wg   = (const float*)d_in[1];
    const float* bg   = (const float*)d_in[2];
    const float* bias = (const float*)d_in[3];
    const float* W1   = (const float*)d_in[4];
    const float* b1   = (const float*)d_in[5];
    const float* W2   = (const float*)d_in[6];
    const float* b2   = (const float*)d_in[7];
    float* out = (float*)d_out;

    cudaFuncSetAttribute(expert_kernel,
                         cudaFuncAttributeMaxDynamicSharedMemorySize, SMEM_BYTES);

    init_kernel<<<2560, 256>>>(x, Wg, bg, bias, W1, W2);
    expert_kernel<<<EGRID, ETHREADS, SMEM_BYTES>>>(x, b1, b2, out);
}

// round 9
// speedup vs baseline: 1.5513x; 1.5513x over previous
#include <cuda_runtime.h>
#include <cuda_fp16.h>
#include <math.h>
#include <stdint.h>

#define D_MODEL     256
#define EXPERT_DIM  512
#define NUM_EXPERTS 8
#define T_TOKENS    4096
#define TILE_T      64
#define EGRID       148
#define ETHREADS    512

// u32 (half2) strides
#define XS_U32      132       // 128 data + 4 pad  (bank = 4g+t, conflict-free)
#define HS_U32      36        // 32 data + 4 pad
#define W1S_U32     72        // 64 data + 8 pad   (bank = 8t+g)
#define W2S_U32     264       // 256 data + 8 pad  (bank = 8t+g)
#define STAGE_U32   4224      // max(32*72=2304, 16*264=4224)
#define NSLOT       4
#define NSTAGE      48        // 8 chunks * (4 W1 + 2 W2)

#define XS_OFF      0
#define HS_OFF      (XS_OFF + TILE_T * XS_U32)          // 8448
#define WST_OFF     (HS_OFF + TILE_T * HS_U32)          // 10752
#define CTRL_OFF    (WST_OFF + NSLOT * STAGE_U32)       // 27648
#define SMEM_U32    (CTRL_OFF + 192)
#define SMEM_BYTES  (SMEM_U32 * 4)                      // ~111 KB

// ---- device scratch ----
__device__ int      g_cnt[NUM_EXPERTS];
__device__ int      g_tok [NUM_EXPERTS][T_TOKENS];
__device__ float    g_wt  [NUM_EXPERTS][T_TOKENS];
__device__ int      g_slot[NUM_EXPERTS][T_TOKENS];
__device__ float    g_scratch[2][T_TOKENS][D_MODEL];
// half2-packed weights along K: g_W1pk[e][k2][h]  k2 in [0,128), h in [0,512)
//                               g_W2pk[e][k2][d]  k2 in [0,256), d in [0,256)
__device__ uint32_t g_W1pk[NUM_EXPERTS * 128 * 512];
__device__ uint32_t g_W2pk[NUM_EXPERTS * 256 * 256];
__device__ int      g_done;
__device__ int      g_done2;

// ---------------------------------------------------------------------------
__device__ __forceinline__ uint32_t pack_h2(float lo, float hi) {
    __half2 h;
    h.x = __float2half_rn(lo);
    h.y = __float2half_rn(hi);
    return *reinterpret_cast<uint32_t*>(&h);
}

__device__ __forceinline__ void mma_f16(float c[4], const uint32_t a[4],
                                        uint32_t b0, uint32_t b1) {
    asm volatile(
        "mma.sync.aligned.m16n8k16.row.col.f32.f16.f16.f32 "
        "{%0,%1,%2,%3}, {%4,%5,%6,%7}, {%8,%9}, {%0,%1,%2,%3};\n"
        : "+f"(c[0]), "+f"(c[1]), "+f"(c[2]), "+f"(c[3])
        : "r"(a[0]), "r"(a[1]), "r"(a[2]), "r"(a[3]), "r"(b0), "r"(b1));
}

__device__ __forceinline__ void cp16(uint32_t dst, const void* src) {
    asm volatile("cp.async.ca.shared.global [%0], [%1], 16;" :: "r"(dst), "l"(src));
}
__device__ __forceinline__ void cp_commit() { asm volatile("cp.async.commit_group;"); }
__device__ __forceinline__ void cp_wait2()  { asm volatile("cp.async.wait_group 2;"); }
__device__ __forceinline__ void cp_wait0()  { asm volatile("cp.async.wait_group 0;"); }

// ---------------------------------------------------------------------------
// Fused init: blocks [0,512) route; [512,2560) pack W1; [2560,4608) pack W2.
__global__ void init_kernel(const float* __restrict__ x,
                            const float* __restrict__ Wg,
                            const float* __restrict__ bg,
                            const float* __restrict__ bias,
                            const float* __restrict__ W1,
                            const float* __restrict__ W2) {
    int bid = blockIdx.x, tid = threadIdx.x;

    if (bid < 512) {
        // ---------------- routing: one warp per token ----------------
        int warp = (bid * 256 + tid) >> 5;
        int lane = tid & 31;
        int t = warp;
        const float* xr = x + (size_t)t * D_MODEL;
        float acc[NUM_EXPERTS];
#pragma unroll
        for (int e = 0; e < NUM_EXPERTS; e++) acc[e] = 0.f;
#pragma unroll
        for (int j = 0; j < D_MODEL / 32; j++) {
            int k = lane + j * 32;
            float xv = xr[k];
            const float4* wrow = (const float4*)(Wg + (size_t)k * NUM_EXPERTS);
            float4 w0 = wrow[0], w1 = wrow[1];
            acc[0] += xv * w0.x; acc[1] += xv * w0.y;
            acc[2] += xv * w0.z; acc[3] += xv * w0.w;
            acc[4] += xv * w1.x; acc[5] += xv * w1.y;
            acc[6] += xv * w1.z; acc[7] += xv * w1.w;
        }
#pragma unroll
        for (int e = 0; e < NUM_EXPERTS; e++)
#pragma unroll
            for (int off = 16; off > 0; off >>= 1)
                acc[e] += __shfl_xor_sync(0xffffffffu, acc[e], off);
        if (lane == 0) {
            float best = -INFINITY, second = -INFINITY;
            int b0 = 0, b1 = 0;
#pragma unroll
            for (int e = 0; e < NUM_EXPERTS; e++) {
                float v = acc[e] + bg[e] + bias[e];
                if (v > best)        { second = best; b1 = b0; best = v; b0 = e; }
                else if (v > second) { second = v; b1 = e; }
            }
            float e1  = expf(second - best);
            float inv = 1.f / (1.f + e1);
            int p0 = atomicAdd(&g_cnt[b0], 1);
            g_tok[b0][p0] = t; g_wt[b0][p0] = inv;      g_slot[b0][p0] = 0;
            int p1 = atomicAdd(&g_cnt[b1], 1);
            g_tok[b1][p1] = t; g_wt[b1][p1] = e1 * inv; g_slot[b1][p1] = 1;
        }
    } else if (bid < 2560) {
        // W1 pack: j over 8*128*512
        int j = (bid - 512) * 256 + tid;
        int n  = j & 511;
        int k2 = (j >> 9) & 127;
        int e  = j >> 16;
        const float* src = W1 + (size_t)e * 131072 + (size_t)(2 * k2) * 512 + n;
        g_W1pk[j] = pack_h2(src[0], src[512]);
    } else {
        // W2 pack: j over 8*256*256
        int j = (bid - 2560) * 256 + tid;
        int n  = j & 255;
        int k2 = (j >> 8) & 255;
        int e  = j >> 16;
        const float* src = W2 + (size_t)e * 131072 + (size_t)(2 * k2) * 256 + n;
        g_W2pk[j] = pack_h2(src[0], src[256]);
    }
}

// ---------------------------------------------------------------------------
// 148 blocks x 512 threads: 16 warps = 2m(x2 subtiles) x 8n over 64-token tile.
// fp16 m16n8k16 mma, 48-stage cp.async ring (4 slots, 2-stage look-ahead).
__global__ void __launch_bounds__(ETHREADS, 1)
expert_kernel(const float* __restrict__ x,
              const float* __restrict__ b1,
              const float* __restrict__ b2,
              float* __restrict__ out) {
    extern __shared__ uint32_t sm[];
    uint32_t* Xs  = sm + XS_OFF;        // [64][132] half2
    uint32_t* Hs  = sm + HS_OFF;        // [64][36]  half2
    uint32_t* Wst = sm + WST_OFF;       // [4][4224] half2
    int*   s_tok  = (int*)(sm + CTRL_OFF);
    float* s_wt   = (float*)(s_tok + TILE_T);
    int*   s_slot = (int*)(s_wt + TILE_T);

    int tid  = threadIdx.x;
    int wid  = tid >> 5;
    int wm   = wid >> 3;        // 0..1: rows wm*32 .. +32 (2 subtiles of 16)
    int wn   = wid & 7;         // 0..7
    int lane = tid & 31;
    int g = lane >> 2, t = lane & 3;

    // inline scheduler
    int cnt[NUM_EXPERTS], off[NUM_EXPERTS + 1];
    off[0] = 0;
#pragma unroll
    for (int e = 0; e < NUM_EXPERTS; e++) {
        cnt[e] = g_cnt[e];
        off[e + 1] = off[e] + (cnt[e] + TILE_T - 1) / TILE_T;
    }
    int total = off[NUM_EXPERTS];

    uint32_t wst_sa = (uint32_t)__cvta_generic_to_shared(Wst);

    for (int it = blockIdx.x; it < total; it += EGRID) {
        int e = 0;
#pragma unroll
        for (int k = 1; k < NUM_EXPERTS; k++)
            if (it >= off[k]) e = k;
        int start = (it - off[e]) * TILE_T;
        int m = min(TILE_T, cnt[e] - start);

        const uint32_t* W1p = g_W1pk + (size_t)e * 128 * 512;
        const uint32_t* W2p = g_W2pk + (size_t)e * 256 * 256;
        const float* b1e = b1 + e * EXPERT_DIM;
        const float* b2e = b2 + e * D_MODEL;

        // stage s: c = s/6, j = s%6.
        //  j<4 : W1 k2-rows j*32..+32, cols c*64..+64 -> [32][72]  (512 cp16)
        //  j>=4: W2 k2-rows c*32+(j-4)*16..+16, 256 cols -> [16][264] (1024 cp16)
        auto issue_stage = [&](int s) {
            int slot = s & (NSLOT - 1);
            int c = s / 6, j = s % 6;
            uint32_t base = wst_sa + (uint32_t)(slot * STAGE_U32) * 4u;
            if (j < 4) {
                int row = tid >> 4, q = tid & 15;       // 32 rows x 16 cp16
                cp16(base + (uint32_t)(row * W1S_U32 + q * 4) * 4u,
                     W1p + (size_t)(j * 32 + row) * 512 + c * 64 + q * 4);
            } else {
#pragma unroll
                for (int i = 0; i < 2; i++) {           // 16 rows x 64 cp16
                    int o = tid + 512 * i;
                    int row = o >> 6, q = o & 63;
                    cp16(base + (uint32_t)(row * W2S_U32 + q * 4) * 4u,
                         W2p + (size_t)(c * 32 + (j - 4) * 16 + row) * 256 + q * 4);
                }
            }
        };

        __syncthreads();
        if (tid < TILE_T) {
            if (tid < m) {
                s_tok[tid]  = g_tok [e][start + tid];
                s_wt[tid]   = g_wt  [e][start + tid];
                s_slot[tid] = g_slot[e][start + tid];
            } else {
                s_tok[tid] = 0; s_wt[tid] = 0.f; s_slot[tid] = 0;
            }
        }
        issue_stage(0); cp_commit();
        issue_stage(1); cp_commit();
        issue_stage(2); cp_commit();
        __syncthreads();

        // gather X tile -> half2 pairs: 64 rows x 64 float4
#pragma unroll
        for (int i = 0; i < 8; i++) {
            int idx = tid + i * ETHREADS;
            int row = idx >> 6, q = idx & 63;
            float4 v = make_float4(0.f, 0.f, 0.f, 0.f);
            if (row < m)
                v = ((const float4*)(x + (size_t)s_tok[row] * D_MODEL))[q];
            uint2 p;
            p.x = pack_h2(v.x, v.y);
            p.y = pack_h2(v.z, v.w);
            *((uint2*)&Xs[row * XS_U32 + q * 2]) = p;
        }

        float acc2[2][4][4];
#pragma unroll
        for (int mt = 0; mt < 2; mt++)
#pragma unroll
            for (int f = 0; f < 4; f++)
#pragma unroll
                for (int r = 0; r < 4; r++) acc2[mt][f][r] = 0.f;
        float c1[2][4];

        for (int s = 0; s < NSTAGE; s++) {
            if (s >= NSTAGE - 2) cp_wait0(); else cp_wait2();
            __syncthreads();
            if (s + 3 < NSTAGE) { issue_stage(s + 3); cp_commit(); }

            int c = s / 6, j = s % 6;
            const uint32_t* Ws = Wst + (s & (NSLOT - 1)) * STAGE_U32;

            if (j < 4) {
                // ---- GEMM1 stage: 4 ksteps (K=64), warp n-slice = 8 cols ----
                if (j == 0) {
#pragma unroll
                    for (int mt = 0; mt < 2; mt++)
#pragma unroll
                        for (int r = 0; r < 4; r++) c1[mt][r] = 0.f;
                }
#pragma unroll
                for (int ks = 0; ks < 4; ks++) {
                    int k2a = j * 32 + ks * 8 + t;      // global k2 for a0/a1
                    uint32_t a[2][4];
#pragma unroll
                    for (int mt = 0; mt < 2; mt++) {
                        int r0 = wm * 32 + mt * 16 + g;
                        a[mt][0] = Xs[r0 * XS_U32 + k2a];
                        a[mt][1] = Xs[(r0 + 8) * XS_U32 + k2a];
                        a[mt][2] = Xs[r0 * XS_U32 + k2a + 4];
                        a[mt][3] = Xs[(r0 + 8) * XS_U32 + k2a + 4];
                    }
                    int col = wn * 8 + g;
                    uint32_t b0 = Ws[(ks * 8 + t) * W1S_U32 + col];
                    uint32_t bv = Ws[(ks * 8 + t + 4) * W1S_U32 + col];
                    mma_f16(c1[0], a[0], b0, bv);
                    mma_f16(c1[1], a[1], b0, bv);
                }
                if (j == 3) {
                    // bias + relu -> half2 Hs[row][k2local], k2local = wn*4+t
                    float bv0 = b1e[c * 64 + wn * 8 + 2 * t];
                    float bv1 = b1e[c * 64 + wn * 8 + 2 * t + 1];
#pragma unroll
                    for (int mt = 0; mt < 2; mt++) {
                        int r0 = wm * 32 + mt * 16 + g;
                        Hs[r0 * HS_U32 + wn * 4 + t] =
                            pack_h2(fmaxf(c1[mt][0] + bv0, 0.f),
                                    fmaxf(c1[mt][1] + bv1, 0.f));
                        Hs[(r0 + 8) * HS_U32 + wn * 4 + t] =
                            pack_h2(fmaxf(c1[mt][2] + bv0, 0.f),
                                    fmaxf(c1[mt][3] + bv1, 0.f));
                    }
                }
            } else {
                // ---- GEMM2 stage: 2 ksteps, warp n-slice = 32 cols ----
#pragma unroll
                for (int ks = 0; ks < 2; ks++) {
                    int k2l = (j - 4) * 16 + ks * 8 + t;    // local k2 in chunk
                    uint32_t a[2][4];
#pragma unroll
                    for (int mt = 0; mt < 2; mt++) {
                        int r0 = wm * 32 + mt * 16 + g;
                        a[mt][0] = Hs[r0 * HS_U32 + k2l];
                        a[mt][1] = Hs[(r0 + 8) * HS_U32 + k2l];
                        a[mt][2] = Hs[r0 * HS_U32 + k2l + 4];
                        a[mt][3] = Hs[(r0 + 8) * HS_U32 + k2l + 4];
                    }
#pragma unroll
                    for (int f = 0; f < 4; f++) {
                        int col = wn * 32 + 8 * f + g;
                        uint32_t b0 = Ws[(ks * 8 + t) * W2S_U32 + col];
                        uint32_t bv = Ws[(ks * 8 + t + 4) * W2S_U32 + col];
                        mma_f16(acc2[0][f], a[0], b0, bv);
                        mma_f16(acc2[1][f], a[1], b0, bv);
                    }
                }
            }
        }

        // ---- epilogue: scratch[slot][tok][col] = w * (acc + b2) ----
#pragma unroll
        for (int mt = 0; mt < 2; mt++) {
#pragma unroll
            for (int hr = 0; hr < 2; hr++) {
                int r = wm * 32 + mt * 16 + g + 8 * hr;
                if (r < m) {
                    float wgt = s_wt[r];
                    float* op = &g_scratch[s_slot[r]][s_tok[r]][0];
#pragma unroll
                    for (int f = 0; f < 4; f++) {
                        int col = wn * 32 + 8 * f + 2 * t;
                        float2 o;
                        o.x = wgt * (acc2[mt][f][2 * hr + 0] + b2e[col]);
                        o.y = wgt * (acc2[mt][f][2 * hr + 1] + b2e[col + 1]);
                        *((float2*)(op + col)) = o;
                    }
                }
            }
        }
    }

    // ================= spin barrier + fused combine =================
    __threadfence();
    __syncthreads();
    if (tid == 0) {
        atomicAdd(&g_done, 1);
        while (*((volatile int*)&g_done) < EGRID) { }
    }
    __syncthreads();
    __threadfence();

    const float4* s0 = (const float4*)g_scratch[0];
    const float4* s1 = (const float4*)g_scratch[1];
    float4* o4 = (float4*)out;
    const int N4 = T_TOKENS * D_MODEL / 4;
    for (int i = blockIdx.x * ETHREADS + tid; i < N4; i += EGRID * ETHREADS) {
        float4 a = s0[i], b = s1[i];
        float4 o;
        o.x = a.x + b.x; o.y = a.y + b.y; o.z = a.z + b.z; o.w = a.w + b.w;
        o4[i] = o;
    }

    // ---- last block resets counters for next graph replay ----
    __threadfence();
    __syncthreads();
    if (tid == 0) {
        int v = atomicAdd(&g_done2, 1);
        if (v == EGRID - 1) {
            g_done = 0; g_done2 = 0;
#pragma unroll
            for (int e = 0; e < NUM_EXPERTS; e++) g_cnt[e] = 0;
        }
    }
}

// ---------------------------------------------------------------------------
extern "C" void kernel_launch(void* const* d_in, const int* in_sizes, int n_in,
                              void* d_out, int out_size) {
    const float* x    = (const float*)d_in[0];
    const float* Wg   = (const float*)d_in[1];
    const float* bg   = (const float*)d_in[2];
    const float* bias = (const float*)d_in[3];
    const float* W1   = (const float*)d_in[4];
    const float* b1   = (const float*)d_in[5];
    const float* W2   = (const float*)d_in[6];
    const float* b2   = (const float*)d_in[7];
    float* out = (float*)d_out;

    cudaFuncSetAttribute(expert_kernel,
                         cudaFuncAttributeMaxDynamicSharedMemorySize, SMEM_BYTES);

    init_kernel<<<4608, 256>>>(x, Wg, bg, bias, W1, W2);
    expert_kernel<<<EGRID, ETHREADS, SMEM_BYTES>>>(x, b1, b2, out);
}

// round 10
// speedup vs baseline: 1.7125x; 1.1039x over previous
#include <cuda_runtime.h>
#include <cuda_fp16.h>
#include <math.h>
#include <stdint.h>

#define D_MODEL     256
#define EXPERT_DIM  512
#define NUM_EXPERTS 8
#define T_TOKENS    4096
#define TILE_T      64
#define EGRID       148
#define ETHREADS    512

// u32 (half2) strides inside a stage
#define XS_U32      132       // 128 data + 4 pad
#define HS_U32      36        // 32 data + 4 pad
#define W1S_U32     72        // 64 data + 8 pad
#define W2S_U32     264       // 256 data + 8 pad

#define W1STG_U     (32 * W1S_U32)          // 2304 u32 = 9216 B
#define W2STG_U     (16 * W2S_U32)          // 4224 u32 = 16896 B
#define CHUNK_U     (4 * W1STG_U + 2 * W2STG_U)   // 17664
#define EXPERT_U    (8 * CHUNK_U)                 // 141312
#define NSLOT       4
#define NSTAGE      48
#define SLOT_U32    W2STG_U                 // 4224 u32, 16896 B (128-mult)

#define XS_OFF      0
#define HS_OFF      (XS_OFF + TILE_T * XS_U32)          // 8448
#define WST_OFF     (HS_OFF + TILE_T * HS_U32)          // 10752 u32 (43008 B, 128-mult)
#define CTRL_OFF    (WST_OFF + NSLOT * SLOT_U32)        // 27648
#define SMEM_U32    (CTRL_OFF + 256)
#define SMEM_BYTES  (SMEM_U32 * 4)

// ---- device scratch ----
__device__ int      g_cnt[NUM_EXPERTS];
__device__ int      g_tok [NUM_EXPERTS][T_TOKENS];
__device__ float    g_wt  [NUM_EXPERTS][T_TOKENS];
__device__ int      g_slot[NUM_EXPERTS][T_TOKENS];
__device__ float    g_scratch[2][T_TOKENS][D_MODEL];
// stage-major padded fp16 weight blob (exact smem image per stage)
__device__ __align__(128) uint32_t g_Wblob[NUM_EXPERTS * EXPERT_U];
__device__ int      g_done;
__device__ int      g_done2;

// ---------------------------------------------------------------------------
__device__ __forceinline__ uint32_t pack_h2(float lo, float hi) {
    __half2 h;
    h.x = __float2half_rn(lo);
    h.y = __float2half_rn(hi);
    return *reinterpret_cast<uint32_t*>(&h);
}

__device__ __forceinline__ void mma_f16(float c[4], const uint32_t a[4],
                                        uint32_t b0, uint32_t b1) {
    asm volatile(
        "mma.sync.aligned.m16n8k16.row.col.f32.f16.f16.f32 "
        "{%0,%1,%2,%3}, {%4,%5,%6,%7}, {%8,%9}, {%0,%1,%2,%3};\n"
        : "+f"(c[0]), "+f"(c[1]), "+f"(c[2]), "+f"(c[3])
        : "r"(a[0]), "r"(a[1]), "r"(a[2]), "r"(a[3]), "r"(b0), "r"(b1));
}

#define MBAR_INIT(mb, n)  asm volatile("mbarrier.init.shared.b64 [%0], %1;" :: "r"(mb), "r"(n) : "memory")
#define MBAR_EXPECT_TX(mb, tx) asm volatile("mbarrier.arrive.expect_tx.shared.b64 _, [%0], %1;" :: "r"(mb), "r"(tx) : "memory")

__device__ __forceinline__ void cp_bulk(uint32_t dst, const void* src,
                                        uint32_t bytes, uint32_t mbar) {
    asm volatile(
        "cp.async.bulk.shared::cta.global.mbarrier::complete_tx::bytes "
        "[%0], [%1], %2, [%3];"
        :: "r"(dst), "l"(src), "r"(bytes), "r"(mbar) : "memory");
}

#define MBAR_WAIT(mb, ph) do { \
    uint32_t _mb = (mb), _ph = (ph), _done; \
    asm volatile("{\n\t.reg .pred p;\n\t" \
        "mbarrier.try_wait.parity.acquire.cta.shared::cta.b64 p, [%1], %2;\n\t" \
        "selp.b32 %0, 1, 0, p;\n\t}" : "=r"(_done) : "r"(_mb), "r"(_ph) : "memory"); \
    if (!_done) { \
        asm volatile("{\n\t.reg .pred P1;\n\t" \
            "WL_%=:\n\t" \
            "mbarrier.try_wait.parity.acquire.cta.shared::cta.b64 P1, [%0], %1, 0x989680;\n\t" \
            "@P1 bra.uni WD_%=;\n\t" \
            "bra.uni WL_%=;\n\t" \
            "WD_%=:\n\t}" :: "r"(_mb), "r"(_ph) : "memory"); \
    } \
} while (0)

// ---------------------------------------------------------------------------
// Fused init: [0,512) route; [512,2560) pack W1 -> blob; [2560,4608) pack W2.
__global__ void init_kernel(const float* __restrict__ x,
                            const float* __restrict__ Wg,
                            const float* __restrict__ bg,
                            const float* __restrict__ bias,
                            const float* __restrict__ W1,
                            const float* __restrict__ W2) {
    int bid = blockIdx.x, tid = threadIdx.x;

    if (bid < 512) {
        int warp = (bid * 256 + tid) >> 5;
        int lane = tid & 31;
        int t = warp;
        const float* xr = x + (size_t)t * D_MODEL;
        float acc[NUM_EXPERTS];
#pragma unroll
        for (int e = 0; e < NUM_EXPERTS; e++) acc[e] = 0.f;
#pragma unroll
        for (int j = 0; j < D_MODEL / 32; j++) {
            int k = lane + j * 32;
            float xv = xr[k];
            const float4* wrow = (const float4*)(Wg + (size_t)k * NUM_EXPERTS);
            float4 w0 = wrow[0], w1 = wrow[1];
            acc[0] += xv * w0.x; acc[1] += xv * w0.y;
            acc[2] += xv * w0.z; acc[3] += xv * w0.w;
            acc[4] += xv * w1.x; acc[5] += xv * w1.y;
            acc[6] += xv * w1.z; acc[7] += xv * w1.w;
        }
#pragma unroll
        for (int e = 0; e < NUM_EXPERTS; e++)
#pragma unroll
            for (int off = 16; off > 0; off >>= 1)
                acc[e] += __shfl_xor_sync(0xffffffffu, acc[e], off);
        if (lane == 0) {
            float best = -INFINITY, second = -INFINITY;
            int b0 = 0, b1 = 0;
#pragma unroll
            for (int e = 0; e < NUM_EXPERTS; e++) {
                float v = acc[e] + bg[e] + bias[e];
                if (v > best)        { second = best; b1 = b0; best = v; b0 = e; }
                else if (v > second) { second = v; b1 = e; }
            }
            float e1  = expf(second - best);
            float inv = 1.f / (1.f + e1);
            int p0 = atomicAdd(&g_cnt[b0], 1);
            g_tok[b0][p0] = t; g_wt[b0][p0] = inv;      g_slot[b0][p0] = 0;
            int p1 = atomicAdd(&g_cnt[b1], 1);
            g_tok[b1][p1] = t; g_wt[b1][p1] = e1 * inv; g_slot[b1][p1] = 1;
        }
    } else if (bid < 2560) {
        // W1 -> blob: j over 8 * 128 * 512  (e, k2, h)
        int j = (bid - 512) * 256 + tid;
        int h  = j & 511;
        int k2 = (j >> 9) & 127;
        int e  = j >> 16;
        const float* src = W1 + (size_t)e * 131072 + (size_t)(2 * k2) * 512 + h;
        int c = h >> 6, js = k2 >> 5, row = k2 & 31, q = h & 63;
        g_Wblob[(size_t)e * EXPERT_U + c * CHUNK_U + js * W1STG_U
                + row * W1S_U32 + q] = pack_h2(src[0], src[512]);
    } else {
        // W2 -> blob: j over 8 * 256 * 256  (e, k2, d)
        int j = (bid - 2560) * 256 + tid;
        int d  = j & 255;
        int k2 = (j >> 8) & 255;
        int e  = j >> 16;
        const float* src = W2 + (size_t)e * 131072 + (size_t)(2 * k2) * 256 + d;
        int c = k2 >> 5, jj = (k2 >> 4) & 1, row = k2 & 15;
        g_Wblob[(size_t)e * EXPERT_U + c * CHUNK_U + 4 * W1STG_U + jj * W2STG_U
                + row * W2S_U32 + d] = pack_h2(src[0], src[256]);
    }
}

// ---------------------------------------------------------------------------
// 148 blocks x 512 threads (16 warps = 2m x 8n). Weight stages via
// cp.async.bulk (TMA DMA) into a 4-slot mbarrier ring, look-ahead 3.
__global__ void __launch_bounds__(ETHREADS, 1)
expert_kernel(const float* __restrict__ x,
              const float* __restrict__ b1,
              const float* __restrict__ b2,
              float* __restrict__ out) {
    extern __shared__ uint32_t sm[];
    uint32_t* Xs  = sm + XS_OFF;        // [64][132] half2
    uint32_t* Hs  = sm + HS_OFF;        // [64][36]  half2
    uint32_t* Wst = sm + WST_OFF;       // [4][4224] half2
    uint64_t* mbv = (uint64_t*)(sm + CTRL_OFF);         // 4 mbarriers
    int*   s_tok  = (int*)(sm + CTRL_OFF + 8);
    float* s_wt   = (float*)(s_tok + TILE_T);
    int*   s_slot = (int*)(s_wt + TILE_T);

    int tid  = threadIdx.x;
    int wid  = tid >> 5;
    int wm   = wid >> 3;        // 0..1
    int wn   = wid & 7;         // 0..7
    int lane = tid & 31;
    int g = lane >> 2, t = lane & 3;

    uint32_t wst_sa  = (uint32_t)__cvta_generic_to_shared(Wst);
    uint32_t mbar_sa = (uint32_t)__cvta_generic_to_shared(mbv);

    if (tid == 0) {
#pragma unroll
        for (int i = 0; i < NSLOT; i++) MBAR_INIT(mbar_sa + i * 8, 1);
    }
    __syncthreads();

    // inline scheduler
    int cnt[NUM_EXPERTS], off[NUM_EXPERTS + 1];
    off[0] = 0;
#pragma unroll
    for (int e = 0; e < NUM_EXPERTS; e++) {
        cnt[e] = g_cnt[e];
        off[e + 1] = off[e] + (cnt[e] + TILE_T - 1) / TILE_T;
    }
    int total = off[NUM_EXPERTS];

    int gs = 0;   // absolute stage counter (slot = gs&3, parity = (gs>>2)&1)

    for (int it = blockIdx.x; it < total; it += EGRID) {
        int e = 0;
#pragma unroll
        for (int k = 1; k < NUM_EXPERTS; k++)
            if (it >= off[k]) e = k;
        int start = (it - off[e]) * TILE_T;
        int m = min(TILE_T, cnt[e] - start);

        const uint32_t* blob = g_Wblob + (size_t)e * EXPERT_U;
        const float* b1e = b1 + e * EXPERT_DIM;
        const float* b2e = b2 + e * D_MODEL;

        // stage s (0..47): c = s/6, j = s%6.
        auto issue_stage = [&](int s) {      // tid 0 only
            int a = gs + s;
            int slot = a & (NSLOT - 1);
            int c = s / 6, j = s % 6;
            uint32_t dst = wst_sa + (uint32_t)(slot * SLOT_U32) * 4u;
            const uint32_t* src = blob + c * CHUNK_U
                + (j < 4 ? j * W1STG_U : 4 * W1STG_U + (j - 4) * W2STG_U);
            uint32_t bytes = (j < 4) ? (W1STG_U * 4u) : (W2STG_U * 4u);
            uint32_t mb = mbar_sa + slot * 8;
            MBAR_EXPECT_TX(mb, bytes);
            cp_bulk(dst, src, bytes, mb);
        };

        __syncthreads();
        if (tid < TILE_T) {
            if (tid < m) {
                s_tok[tid]  = g_tok [e][start + tid];
                s_wt[tid]   = g_wt  [e][start + tid];
                s_slot[tid] = g_slot[e][start + tid];
            } else {
                s_tok[tid] = 0; s_wt[tid] = 0.f; s_slot[tid] = 0;
            }
        }
        if (tid == 0) { issue_stage(0); issue_stage(1); issue_stage(2); }
        __syncthreads();

        // gather X tile -> half2 pairs: 64 rows x 64 float4
#pragma unroll
        for (int i = 0; i < 8; i++) {
            int idx = tid + i * ETHREADS;
            int row = idx >> 6, q = idx & 63;
            float4 v = make_float4(0.f, 0.f, 0.f, 0.f);
            if (row < m)
                v = ((const float4*)(x + (size_t)s_tok[row] * D_MODEL))[q];
            uint2 p;
            p.x = pack_h2(v.x, v.y);
            p.y = pack_h2(v.z, v.w);
            *((uint2*)&Xs[row * XS_U32 + q * 2]) = p;
        }

        float acc2[2][4][4];
#pragma unroll
        for (int mt = 0; mt < 2; mt++)
#pragma unroll
            for (int f = 0; f < 4; f++)
#pragma unroll
                for (int r = 0; r < 4; r++) acc2[mt][f][r] = 0.f;
        float c1[2][4];

        for (int s = 0; s < NSTAGE; s++) {
            int a = gs + s;
            MBAR_WAIT(mbar_sa + (a & (NSLOT - 1)) * 8, (a >> 2) & 1);
            __syncthreads();             // all warps past stage s-1 compute
            if (tid == 0 && s + 3 < NSTAGE) issue_stage(s + 3);

            int c = s / 6, j = s % 6;
            const uint32_t* Ws = Wst + (a & (NSLOT - 1)) * SLOT_U32;

            if (j < 4) {
                // ---- GEMM1 stage: K=64 (4 ksteps), warp n-slice = 8 cols ----
                if (j == 0) {
#pragma unroll
                    for (int mt = 0; mt < 2; mt++)
#pragma unroll
                        for (int r = 0; r < 4; r++) c1[mt][r] = 0.f;
                }
#pragma unroll
                for (int ks = 0; ks < 4; ks++) {
                    int k2a = j * 32 + ks * 8 + t;
                    uint32_t aa[2][4];
#pragma unroll
                    for (int mt = 0; mt < 2; mt++) {
                        int r0 = wm * 32 + mt * 16 + g;
                        aa[mt][0] = Xs[r0 * XS_U32 + k2a];
                        aa[mt][1] = Xs[(r0 + 8) * XS_U32 + k2a];
                        aa[mt][2] = Xs[r0 * XS_U32 + k2a + 4];
                        aa[mt][3] = Xs[(r0 + 8) * XS_U32 + k2a + 4];
                    }
                    int col = wn * 8 + g;
                    uint32_t b0 = Ws[(ks * 8 + t) * W1S_U32 + col];
                    uint32_t bv = Ws[(ks * 8 + t + 4) * W1S_U32 + col];
                    mma_f16(c1[0], aa[0], b0, bv);
                    mma_f16(c1[1], aa[1], b0, bv);
                }
                if (j == 3) {
                    float bv0 = b1e[c * 64 + wn * 8 + 2 * t];
                    float bv1 = b1e[c * 64 + wn * 8 + 2 * t + 1];
#pragma unroll
                    for (int mt = 0; mt < 2; mt++) {
                        int r0 = wm * 32 + mt * 16 + g;
                        Hs[r0 * HS_U32 + wn * 4 + t] =
                            pack_h2(fmaxf(c1[mt][0] + bv0, 0.f),
                                    fmaxf(c1[mt][1] + bv1, 0.f));
                        Hs[(r0 + 8) * HS_U32 + wn * 4 + t] =
                            pack_h2(fmaxf(c1[mt][2] + bv0, 0.f),
                                    fmaxf(c1[mt][3] + bv1, 0.f));
                    }
                }
            } else {
                // ---- GEMM2 stage: 2 ksteps, warp n-slice = 32 cols ----
#pragma unroll
                for (int ks = 0; ks < 2; ks++) {
                    int k2l = (j - 4) * 16 + ks * 8 + t;
                    uint32_t aa[2][4];
#pragma unroll
                    for (int mt = 0; mt < 2; mt++) {
                        int r0 = wm * 32 + mt * 16 + g;
                        aa[mt][0] = Hs[r0 * HS_U32 + k2l];
                        aa[mt][1] = Hs[(r0 + 8) * HS_U32 + k2l];
                        aa[mt][2] = Hs[r0 * HS_U32 + k2l + 4];
                        aa[mt][3] = Hs[(r0 + 8) * HS_U32 + k2l + 4];
                    }
#pragma unroll
                    for (int f = 0; f < 4; f++) {
                        int col = wn * 32 + 8 * f + g;
                        uint32_t b0 = Ws[(ks * 8 + t) * W2S_U32 + col];
                        uint32_t bv = Ws[(ks * 8 + t + 4) * W2S_U32 + col];
                        mma_f16(acc2[0][f], aa[0], b0, bv);
                        mma_f16(acc2[1][f], aa[1], b0, bv);
                    }
                }
            }
        }
        gs += NSTAGE;

        // ---- epilogue: scratch[slot][tok][col] = w * (acc + b2) ----
#pragma unroll
        for (int mt = 0; mt < 2; mt++) {
#pragma unroll
            for (int hr = 0; hr < 2; hr++) {
                int r = wm * 32 + mt * 16 + g + 8 * hr;
                if (r < m) {
                    float wgt = s_wt[r];
                    float* op = &g_scratch[s_slot[r]][s_tok[r]][0];
#pragma unroll
                    for (int f = 0; f < 4; f++) {
                        int col = wn * 32 + 8 * f + 2 * t;
                        float2 o;
                        o.x = wgt * (acc2[mt][f][2 * hr + 0] + b2e[col]);
                        o.y = wgt * (acc2[mt][f][2 * hr + 1] + b2e[col + 1]);
                        *((float2*)(op + col)) = o;
                    }
                }
            }
        }
    }

    // ================= spin barrier + fused combine =================
    __threadfence();
    __syncthreads();
    if (tid == 0) {
        atomicAdd(&g_done, 1);
        while (*((volatile int*)&g_done) < EGRID) { }
    }
    __syncthreads();
    __threadfence();

    const float4* s0 = (const float4*)g_scratch[0];
    const float4* s1 = (const float4*)g_scratch[1];
    float4* o4 = (float4*)out;
    const int N4 = T_TOKENS * D_MODEL / 4;
    for (int i = blockIdx.x * ETHREADS + tid; i < N4; i += EGRID * ETHREADS) {
        float4 a = s0[i], b = s1[i];
        float4 o;
        o.x = a.x + b.x; o.y = a.y + b.y; o.z = a.z + b.z; o.w = a.w + b.w;
        o4[i] = o;
    }

    // ---- last block resets counters for next graph replay ----
    __threadfence();
    __syncthreads();
    if (tid == 0) {
        int v = atomicAdd(&g_done2, 1);
        if (v == EGRID - 1) {
            g_done = 0; g_done2 = 0;
#pragma unroll
            for (int e = 0; e < NUM_EXPERTS; e++) g_cnt[e] = 0;
        }
    }
}

// ---------------------------------------------------------------------------
extern "C" void kernel_launch(void* const* d_in, const int* in_sizes, int n_in,
                              void* d_out, int out_size) {
    const float* x    = (const float*)d_in[0];
    const float* Wg   = (const float*)d_in[1];
    const float* bg   = (const float*)d_in[2];
    const float* bias = (const float*)d_in[3];
    const float* W1   = (const float*)d_in[4];
    const float* b1   = (const float*)d_in[5];
    const float* W2   = (const float*)d_in[6];
    const float* b2   = (const float*)d_in[7];
    float* out = (float*)d_out;

    cudaFuncSetAttribute(expert_kernel,
                         cudaFuncAttributeMaxDynamicSharedMemorySize, SMEM_BYTES);

    init_kernel<<<4608, 256>>>(x, Wg, bg, bias, W1, W2);
    expert_kernel<<<EGRID, ETHREADS, SMEM_BYTES>>>(x, b1, b2, out);
}

// round 11
// speedup vs baseline: 1.9781x; 1.1551x over previous
#include <cuda_runtime.h>
#include <cuda_fp16.h>
#include <math.h>
#include <stdint.h>

#define D_MODEL     256
#define EXPERT_DIM  512
#define NUM_EXPERTS 8
#define T_TOKENS    4096
#define TILE_T      64
#define EGRID       148
#define ETHREADS    512

// u32 (half2) strides
#define XS_U32      132       // 128 data + 4 pad; bank(row) = 4r -> ldmatrix conflict-free
#define HS_U32      36        // 32 data + 4 pad
#define W1R_U32     72        // 64 data + 8 pad
#define W2R_U32     264       // 256 data + 8 pad

#define W1STG_U     (128 * W1R_U32)         // 9216 u32 = 36864 B (full chunk, K=256)
#define W2STG_U     (32 * W2R_U32)          // 8448 u32 = 33792 B (full chunk, K=64)
#define CHUNK_U     (W1STG_U + W2STG_U)     // 17664
#define EXPERT_U    (8 * CHUNK_U)           // 141312
#define NSLOT       3
#define NSTAGE      16                      // 8 chunks * (W1 + W2)
#define SLOT_U32    W1STG_U                 // 9216

#define XS_OFF      0
#define HS_OFF      (XS_OFF + TILE_T * XS_U32)          // 8448
#define WST_OFF     (HS_OFF + TILE_T * HS_U32)          // 10752 (43008 B, 128-mult)
#define CTRL_OFF    (WST_OFF + NSLOT * SLOT_U32)        // 38400
#define SMEM_U32    (CTRL_OFF + 256)
#define SMEM_BYTES  (SMEM_U32 * 4)                      // ~154.6 KB

// ---- device scratch ----
__device__ int      g_cnt[NUM_EXPERTS];
__device__ int      g_tok [NUM_EXPERTS][T_TOKENS];
__device__ float    g_wt  [NUM_EXPERTS][T_TOKENS];
__device__ int      g_slot[NUM_EXPERTS][T_TOKENS];
__device__ float    g_scratch[2][T_TOKENS][D_MODEL];
__device__ __align__(128) uint32_t g_Wblob[NUM_EXPERTS * EXPERT_U];
__device__ int      g_done;
__device__ int      g_done2;

// ---------------------------------------------------------------------------
__device__ __forceinline__ uint32_t pack_h2(float lo, float hi) {
    __half2 h;
    h.x = __float2half_rn(lo);
    h.y = __float2half_rn(hi);
    return *reinterpret_cast<uint32_t*>(&h);
}

__device__ __forceinline__ void mma_f16(float c[4], const uint32_t a[4],
                                        uint32_t b0, uint32_t b1) {
    asm volatile(
        "mma.sync.aligned.m16n8k16.row.col.f32.f16.f16.f32 "
        "{%0,%1,%2,%3}, {%4,%5,%6,%7}, {%8,%9}, {%0,%1,%2,%3};\n"
        : "+f"(c[0]), "+f"(c[1]), "+f"(c[2]), "+f"(c[3])
        : "r"(a[0]), "r"(a[1]), "r"(a[2]), "r"(a[3]), "r"(b0), "r"(b1));
}

__device__ __forceinline__ void ldsm_x4(uint32_t a[4], uint32_t addr) {
    asm volatile(
        "ldmatrix.sync.aligned.m8n8.x4.shared.b16 {%0,%1,%2,%3}, [%4];"
        : "=r"(a[0]), "=r"(a[1]), "=r"(a[2]), "=r"(a[3]) : "r"(addr));
}

#define MBAR_INIT(mb, n)  asm volatile("mbarrier.init.shared.b64 [%0], %1;" :: "r"(mb), "r"(n) : "memory")
#define MBAR_EXPECT_TX(mb, tx) asm volatile("mbarrier.arrive.expect_tx.shared.b64 _, [%0], %1;" :: "r"(mb), "r"(tx) : "memory")

__device__ __forceinline__ void cp_bulk(uint32_t dst, const void* src,
                                        uint32_t bytes, uint32_t mbar) {
    asm volatile(
        "cp.async.bulk.shared::cta.global.mbarrier::complete_tx::bytes "
        "[%0], [%1], %2, [%3];"
        :: "r"(dst), "l"(src), "r"(bytes), "r"(mbar) : "memory");
}

#define MBAR_WAIT(mb, ph) do { \
    uint32_t _mb = (mb), _ph = (ph), _done; \
    asm volatile("{\n\t.reg .pred p;\n\t" \
        "mbarrier.try_wait.parity.acquire.cta.shared::cta.b64 p, [%1], %2;\n\t" \
        "selp.b32 %0, 1, 0, p;\n\t}" : "=r"(_done) : "r"(_mb), "r"(_ph) : "memory"); \
    if (!_done) { \
        asm volatile("{\n\t.reg .pred P1;\n\t" \
            "WL_%=:\n\t" \
            "mbarrier.try_wait.parity.acquire.cta.shared::cta.b64 P1, [%0], %1, 0x989680;\n\t" \
            "@P1 bra.uni WD_%=;\n\t" \
            "bra.uni WL_%=;\n\t" \
            "WD_%=:\n\t}" :: "r"(_mb), "r"(_ph) : "memory"); \
    } \
} while (0)

// ---------------------------------------------------------------------------
// Fused init: [0,512) route; [512,2560) pack W1 -> blob; [2560,4608) pack W2.
__global__ void init_kernel(const float* __restrict__ x,
                            const float* __restrict__ Wg,
                            const float* __restrict__ bg,
                            const float* __restrict__ bias,
                            const float* __restrict__ W1,
                            const float* __restrict__ W2) {
    int bid = blockIdx.x, tid = threadIdx.x;

    if (bid < 512) {
        int warp = (bid * 256 + tid) >> 5;
        int lane = tid & 31;
        int t = warp;
        const float* xr = x + (size_t)t * D_MODEL;
        float acc[NUM_EXPERTS];
#pragma unroll
        for (int e = 0; e < NUM_EXPERTS; e++) acc[e] = 0.f;
#pragma unroll
        for (int j = 0; j < D_MODEL / 32; j++) {
            int k = lane + j * 32;
            float xv = xr[k];
            const float4* wrow = (const float4*)(Wg + (size_t)k * NUM_EXPERTS);
            float4 w0 = wrow[0], w1 = wrow[1];
            acc[0] += xv * w0.x; acc[1] += xv * w0.y;
            acc[2] += xv * w0.z; acc[3] += xv * w0.w;
            acc[4] += xv * w1.x; acc[5] += xv * w1.y;
            acc[6] += xv * w1.z; acc[7] += xv * w1.w;
        }
#pragma unroll
        for (int e = 0; e < NUM_EXPERTS; e++)
#pragma unroll
            for (int off = 16; off > 0; off >>= 1)
                acc[e] += __shfl_xor_sync(0xffffffffu, acc[e], off);
        if (lane == 0) {
            float best = -INFINITY, second = -INFINITY;
            int b0 = 0, b1 = 0;
#pragma unroll
            for (int e = 0; e < NUM_EXPERTS; e++) {
                float v = acc[e] + bg[e] + bias[e];
                if (v > best)        { second = best; b1 = b0; best = v; b0 = e; }
                else if (v > second) { second = v; b1 = e; }
            }
            float e1  = expf(second - best);
            float inv = 1.f / (1.f + e1);
            int p0 = atomicAdd(&g_cnt[b0], 1);
            g_tok[b0][p0] = t; g_wt[b0][p0] = inv;      g_slot[b0][p0] = 0;
            int p1 = atomicAdd(&g_cnt[b1], 1);
            g_tok[b1][p1] = t; g_wt[b1][p1] = e1 * inv; g_slot[b1][p1] = 1;
        }
    } else if (bid < 2560) {
        // W1 -> blob stage image: j over 8*128*512 (e, k2, h)
        int j = (bid - 512) * 256 + tid;
        int h  = j & 511;
        int k2 = (j >> 9) & 127;
        int e  = j >> 16;
        const float* src = W1 + (size_t)e * 131072 + (size_t)(2 * k2) * 512 + h;
        int c = h >> 6, col = h & 63;
        g_Wblob[(size_t)e * EXPERT_U + c * CHUNK_U + k2 * W1R_U32 + col] =
            pack_h2(src[0], src[512]);
    } else {
        // W2 -> blob stage image: j over 8*256*256 (e, k2, d)
        int j = (bid - 2560) * 256 + tid;
        int d  = j & 255;
        int k2 = (j >> 8) & 255;
        int e  = j >> 16;
        const float* src = W2 + (size_t)e * 131072 + (size_t)(2 * k2) * 256 + d;
        int c = k2 >> 5, k2l = k2 & 31;
        g_Wblob[(size_t)e * EXPERT_U + c * CHUNK_U + W1STG_U + k2l * W2R_U32 + d] =
            pack_h2(src[0], src[256]);
    }
}

// ---------------------------------------------------------------------------
// 148 blocks x 512 threads (16 warps = 2m x 8n). 16 big stages/item via
// cp.async.bulk into a 3-slot mbarrier ring, ldmatrix A-fragments.
__global__ void __launch_bounds__(ETHREADS, 1)
expert_kernel(const float* __restrict__ x,
              const float* __restrict__ b1,
              const float* __restrict__ b2,
              float* __restrict__ out) {
    extern __shared__ uint32_t sm[];
    uint32_t* Xs  = sm + XS_OFF;        // [64][132] half2
    uint32_t* Hs  = sm + HS_OFF;        // [64][36]  half2
    uint32_t* Wst = sm + WST_OFF;       // [3][9216]
    uint64_t* mbv = (uint64_t*)(sm + CTRL_OFF);
    int*   s_tok  = (int*)(sm + CTRL_OFF + 8);
    float* s_wt   = (float*)(s_tok + TILE_T);
    int*   s_slot = (int*)(s_wt + TILE_T);

    int tid  = threadIdx.x;
    int wid  = tid >> 5;
    int wm   = wid >> 3;        // 0..1
    int wn   = wid & 7;         // 0..7
    int lane = tid & 31;
    int g = lane >> 2, t = lane & 3;

    uint32_t wst_sa  = (uint32_t)__cvta_generic_to_shared(Wst);
    uint32_t xs_sa   = (uint32_t)__cvta_generic_to_shared(Xs);
    uint32_t hs_sa   = (uint32_t)__cvta_generic_to_shared(Hs);
    uint32_t mbar_sa = (uint32_t)__cvta_generic_to_shared(mbv);

    // ldmatrix per-lane address pieces: lanes 0-15 rows, bit4 -> +16B (k 8-15)
    int lrow = lane & 15;
    int lcol = (lane >> 4) * 16;
    // GEMM1 A bases (two m16 subtiles), stride 528 B
    uint32_t xa0 = xs_sa + (uint32_t)((wm * 32 + lrow) * (XS_U32 * 4)) + lcol;
    uint32_t xa1 = xa0 + 16 * (XS_U32 * 4);
    // GEMM2 A bases, stride 144 B
    uint32_t ha0 = hs_sa + (uint32_t)((wm * 32 + lrow) * (HS_U32 * 4)) + lcol;
    uint32_t ha1 = ha0 + 16 * (HS_U32 * 4);

    if (tid == 0) {
#pragma unroll
        for (int i = 0; i < NSLOT; i++) MBAR_INIT(mbar_sa + i * 8, 1);
    }
    __syncthreads();

    // inline scheduler
    int cnt[NUM_EXPERTS], off[NUM_EXPERTS + 1];
    off[0] = 0;
#pragma unroll
    for (int e = 0; e < NUM_EXPERTS; e++) {
        cnt[e] = g_cnt[e];
        off[e + 1] = off[e] + (cnt[e] + TILE_T - 1) / TILE_T;
    }
    int total = off[NUM_EXPERTS];

    int gs = 0;   // absolute stage counter

    for (int it = blockIdx.x; it < total; it += EGRID) {
        int e = 0;
#pragma unroll
        for (int k = 1; k < NUM_EXPERTS; k++)
            if (it >= off[k]) e = k;
        int start = (it - off[e]) * TILE_T;
        int m = min(TILE_T, cnt[e] - start);

        const uint32_t* blob = g_Wblob + (size_t)e * EXPERT_U;
        const float* b1e = b1 + e * EXPERT_DIM;
        const float* b2e = b2 + e * D_MODEL;

        // stage s (0..15): c = s>>1; even = W1 chunk, odd = W2 chunk
        auto issue_stage = [&](int s) {      // tid 0 only
            int a = gs + s;
            int slot = a % NSLOT;
            int c = s >> 1;
            uint32_t dst = wst_sa + (uint32_t)(slot * SLOT_U32) * 4u;
            const uint32_t* src;
            uint32_t bytes;
            if ((s & 1) == 0) { src = blob + c * CHUNK_U;            bytes = W1STG_U * 4u; }
            else              { src = blob + c * CHUNK_U + W1STG_U;  bytes = W2STG_U * 4u; }
            uint32_t mb = mbar_sa + slot * 8;
            MBAR_EXPECT_TX(mb, bytes);
            cp_bulk(dst, src, bytes, mb);
        };

        __syncthreads();
        if (tid < TILE_T) {
            if (tid < m) {
                s_tok[tid]  = g_tok [e][start + tid];
                s_wt[tid]   = g_wt  [e][start + tid];
                s_slot[tid] = g_slot[e][start + tid];
            } else {
                s_tok[tid] = 0; s_wt[tid] = 0.f; s_slot[tid] = 0;
            }
        }
        if (tid == 0) { issue_stage(0); issue_stage(1); }
        __syncthreads();

        // gather X tile -> half2 pairs: 64 rows x 64 float4
#pragma unroll
        for (int i = 0; i < 8; i++) {
            int idx = tid + i * ETHREADS;
            int row = idx >> 6, q = idx & 63;
            float4 v = make_float4(0.f, 0.f, 0.f, 0.f);
            if (row < m)
                v = ((const float4*)(x + (size_t)s_tok[row] * D_MODEL))[q];
            uint2 p;
            p.x = pack_h2(v.x, v.y);
            p.y = pack_h2(v.z, v.w);
            *((uint2*)&Xs[row * XS_U32 + q * 2]) = p;
        }

        float acc2[2][4][4];
#pragma unroll
        for (int mt = 0; mt < 2; mt++)
#pragma unroll
            for (int f = 0; f < 4; f++)
#pragma unroll
                for (int r = 0; r < 4; r++) acc2[mt][f][r] = 0.f;

        for (int s = 0; s < NSTAGE; s++) {
            int a = gs + s;
            int slot = a % NSLOT;
            MBAR_WAIT(mbar_sa + slot * 8, (a / NSLOT) & 1);
            __syncthreads();             // all warps past stage s-1 (slot reuse + Hs WAR)
            if (tid == 0 && s + 2 < NSTAGE) issue_stage(s + 2);

            int c = s >> 1;
            const uint32_t* Ws = Wst + slot * SLOT_U32;

            if ((s & 1) == 0) {
                // ====== GEMM1 stage: full chunk, K=256 (16 ksteps) ======
                float c1[2][4];
#pragma unroll
                for (int mt = 0; mt < 2; mt++)
#pragma unroll
                    for (int r = 0; r < 4; r++) c1[mt][r] = 0.f;
                int col = wn * 8 + g;
#pragma unroll
                for (int ks = 0; ks < 16; ks++) {
                    uint32_t a0[4], a1[4];
                    ldsm_x4(a0, xa0 + ks * 32);
                    ldsm_x4(a1, xa1 + ks * 32);
                    uint32_t b0 = Ws[(ks * 8 + t) * W1R_U32 + col];
                    uint32_t bv = Ws[(ks * 8 + t + 4) * W1R_U32 + col];
                    mma_f16(c1[0], a0, b0, bv);
                    mma_f16(c1[1], a1, b0, bv);
                }
                // bias + relu -> half2 Hs
                float bv0 = b1e[c * 64 + wn * 8 + 2 * t];
                float bv1 = b1e[c * 64 + wn * 8 + 2 * t + 1];
#pragma unroll
                for (int mt = 0; mt < 2; mt++) {
                    int r0 = wm * 32 + mt * 16 + g;
                    Hs[r0 * HS_U32 + wn * 4 + t] =
                        pack_h2(fmaxf(c1[mt][0] + bv0, 0.f),
                                fmaxf(c1[mt][1] + bv1, 0.f));
                    Hs[(r0 + 8) * HS_U32 + wn * 4 + t] =
                        pack_h2(fmaxf(c1[mt][2] + bv0, 0.f),
                                fmaxf(c1[mt][3] + bv1, 0.f));
                }
            } else {
                // ====== GEMM2 stage: full chunk, K=64 (4 ksteps) ======
#pragma unroll
                for (int ks = 0; ks < 4; ks++) {
                    uint32_t a0[4], a1[4];
                    ldsm_x4(a0, ha0 + ks * 32);
                    ldsm_x4(a1, ha1 + ks * 32);
#pragma unroll
                    for (int f = 0; f < 4; f++) {
                        int col = wn * 32 + 8 * f + g;
                        uint32_t b0 = Ws[(ks * 8 + t) * W2R_U32 + col];
                        uint32_t bv = Ws[(ks * 8 + t + 4) * W2R_U32 + col];
                        mma_f16(acc2[0][f], a0, b0, bv);
                        mma_f16(acc2[1][f], a1, b0, bv);
                    }
                }
            }
        }
        gs += NSTAGE;

        // ---- epilogue: scratch[slot][tok][col] = w * (acc + b2) ----
#pragma unroll
        for (int mt = 0; mt < 2; mt++) {
#pragma unroll
            for (int hr = 0; hr < 2; hr++) {
                int r = wm * 32 + mt * 16 + g + 8 * hr;
                if (r < m) {
                    float wgt = s_wt[r];
                    float* op = &g_scratch[s_slot[r]][s_tok[r]][0];
#pragma unroll
                    for (int f = 0; f < 4; f++) {
                        int col = wn * 32 + 8 * f + 2 * t;
                        float2 o;
                        o.x = wgt * (acc2[mt][f][2 * hr + 0] + b2e[col]);
                        o.y = wgt * (acc2[mt][f][2 * hr + 1] + b2e[col + 1]);
                        *((float2*)(op + col)) = o;
                    }
                }
            }
        }
    }

    // ================= spin barrier + fused combine =================
    __threadfence();
    __syncthreads();
    if (tid == 0) {
        atomicAdd(&g_done, 1);
        while (*((volatile int*)&g_done) < EGRID) { }
    }
    __syncthreads();
    __threadfence();

    const float4* s0 = (const float4*)g_scratch[0];
    const float4* s1 = (const float4*)g_scratch[1];
    float4* o4 = (float4*)out;
    const int N4 = T_TOKENS * D_MODEL / 4;
    for (int i = blockIdx.x * ETHREADS + tid; i < N4; i += EGRID * ETHREADS) {
        float4 a = s0[i], b = s1[i];
        float4 o;
        o.x = a.x + b.x; o.y = a.y + b.y; o.z = a.z + b.z; o.w = a.w + b.w;
        o4[i] = o;
    }

    // ---- last block resets counters for next graph replay ----
    __threadfence();
    __syncthreads();
    if (tid == 0) {
        int v = atomicAdd(&g_done2, 1);
        if (v == EGRID - 1) {
            g_done = 0; g_done2 = 0;
#pragma unroll
            for (int e = 0; e < NUM_EXPERTS; e++) g_cnt[e] = 0;
        }
    }
}

// ---------------------------------------------------------------------------
extern "C" void kernel_launch(void* const* d_in, const int* in_sizes, int n_in,
                              void* d_out, int out_size) {
    const float* x    = (const float*)d_in[0];
    const float* Wg   = (const float*)d_in[1];
    const float* bg   = (const float*)d_in[2];
    const float* bias = (const float*)d_in[3];
    const float* W1   = (const float*)d_in[4];
    const float* b1   = (const float*)d_in[5];
    const float* W2   = (const float*)d_in[6];
    const float* b2   = (const float*)d_in[7];
    float* out = (float*)d_out;

    cudaFuncSetAttribute(expert_kernel,
                         cudaFuncAttributeMaxDynamicSharedMemorySize, SMEM_BYTES);

    init_kernel<<<4608, 256>>>(x, Wg, bg, bias, W1, W2);
    expert_kernel<<<EGRID, ETHREADS, SMEM_BYTES>>>(x, b1, b2, out);
}